// round 16
// baseline (speedup 1.0000x reference)
#include <cuda_runtime.h>
#include <cuda_fp16.h>
#include <cstdint>
#include <math.h>

// Problem constants
#define BATCH 4
#define SEQ   2048
#define DMODEL 1024
#define NHEAD 16
#define HDIM  64
#define MROWS (BATCH * SEQ)   // 8192

// Scratch (allocation-free rule: __device__ globals). All fp16 intermediates.
__device__ __half g_Q[(size_t)MROWS * DMODEL];
__device__ __half g_K[(size_t)MROWS * DMODEL];
__device__ __half g_V[(size_t)MROWS * DMODEL];
__device__ __half g_C[(size_t)MROWS * DMODEL];
__device__ __half g_T[3][(size_t)MROWS * DMODEL];   // fp16-rounded activations
__device__ __half g_Wr[4][(size_t)DMODEL * DMODEL]; // fp16-rounded weights

// ---------------------------------------------------------------------------
// Helpers
// ---------------------------------------------------------------------------
__device__ __forceinline__ void mma_f16(float* c, const uint32_t* a, const uint32_t* b) {
    asm volatile(
        "mma.sync.aligned.m16n8k16.row.col.f32.f16.f16.f32 "
        "{%0,%1,%2,%3}, {%4,%5,%6,%7}, {%8,%9}, {%0,%1,%2,%3};"
        : "+f"(c[0]), "+f"(c[1]), "+f"(c[2]), "+f"(c[3])
        : "r"(a[0]), "r"(a[1]), "r"(a[2]), "r"(a[3]), "r"(b[0]), "r"(b[1]));
}
__device__ __forceinline__ uint32_t sm_u32(const void* p) {
    return (uint32_t)__cvta_generic_to_shared(p);
}
__device__ __forceinline__ void ldsm4(uint32_t addr, uint32_t& r0, uint32_t& r1,
                                      uint32_t& r2, uint32_t& r3) {
    asm volatile("ldmatrix.sync.aligned.m8n8.x4.shared.b16 {%0,%1,%2,%3}, [%4];"
                 : "=r"(r0), "=r"(r1), "=r"(r2), "=r"(r3) : "r"(addr));
}
__device__ __forceinline__ void ldsm4t(uint32_t addr, uint32_t& r0, uint32_t& r1,
                                       uint32_t& r2, uint32_t& r3) {
    asm volatile("ldmatrix.sync.aligned.m8n8.x4.trans.shared.b16 {%0,%1,%2,%3}, [%4];"
                 : "=r"(r0), "=r"(r1), "=r"(r2), "=r"(r3) : "r"(addr));
}
__device__ __forceinline__ void cp16(uint32_t saddr, const void* gaddr) {
    asm volatile("cp.async.cg.shared.global [%0], [%1], 16;"
                 :: "r"(saddr), "l"(gaddr));
}
__device__ __forceinline__ void cp_commit() {
    asm volatile("cp.async.commit_group;" ::: "memory");
}
template <int N>
__device__ __forceinline__ void cp_wait() {
    asm volatile("cp.async.wait_group %0;" :: "n"(N) : "memory");
}

// ---------------------------------------------------------------------------
// Batched fp32 -> fp16 rounding (round-to-nearest-even).
// ---------------------------------------------------------------------------
struct Round3Args { const float *i0, *i1, *i2; __half *o0, *o1, *o2; };
__global__ void round3_kernel(Round3Args a, int n4)
{
    int i = blockIdx.x * blockDim.x + threadIdx.x;
    if (i >= n4) return;
    const float* in = (blockIdx.y == 0) ? a.i0 : (blockIdx.y == 1) ? a.i1 : a.i2;
    __half* out     = (blockIdx.y == 0) ? a.o0 : (blockIdx.y == 1) ? a.o1 : a.o2;
    float4 v = ((const float4*)in)[i];
    ((__half2*)out)[2 * i]     = __floats2half2_rn(v.x, v.y);
    ((__half2*)out)[2 * i + 1] = __floats2half2_rn(v.z, v.w);
}
struct Round4Args { const float *i0, *i1, *i2, *i3; __half *o0, *o1, *o2, *o3; };
__global__ void round4_kernel(Round4Args a, int n4)
{
    int i = blockIdx.x * blockDim.x + threadIdx.x;
    if (i >= n4) return;
    const float* in;
    __half* out;
    switch (blockIdx.y) {
        case 0: in = a.i0; out = a.o0; break;
        case 1: in = a.i1; out = a.o1; break;
        case 2: in = a.i2; out = a.o2; break;
        default: in = a.i3; out = a.o3; break;
    }
    float4 v = ((const float4*)in)[i];
    ((__half2*)out)[2 * i]     = __floats2half2_rn(v.x, v.y);
    ((__half2*)out)[2 * i + 1] = __floats2half2_rn(v.z, v.w);
}

// ---------------------------------------------------------------------------
// GEMM core: C[M,N] = A[M,K] @ W[N,K]^T + bias[N], fp16 mma.sync m16n8k16.
// Pre-rounded fp16 inputs. 3-stage cp.async pipeline, ldmatrix consumers.
// CTA tile 128x128, BK=32, 8 warps. block = 256.
// mode 1: half out = rn_f16((acc+bias)*oscale). mode 0: fp32 out.
// ---------------------------------------------------------------------------
#define GSTR 40                       // halves per row (32 + 8 pad), 80 B
#define GTILE (128 * GSTR)            // halves per tile
#define GSTAGE (2 * GTILE)            // A + W
#define GEMM_SMEM (3 * GSTAGE * 2)    // 61,440 B

__device__ __forceinline__ void gemm_body(
    const __half* __restrict__ A, const __half* __restrict__ W,
    const float* __restrict__ bias, void* __restrict__ Cout,
    int mode, float oscale, __half* smg, int m0, int n0)
{
    const int tid  = threadIdx.x;
    const int lane = tid & 31;
    const int wid  = tid >> 5;
    const int wm   = wid & 3;
    const int wn   = wid >> 2;
    const int g    = lane >> 2;
    const int q    = lane & 3;

    const int a_row = (lane & 7) + 8 * ((lane >> 3) & 1);
    const int a_col = 8 * (lane >> 4);
    const int b_row = 8 * (lane >> 4) + (lane & 7);
    const int b_col = 8 * ((lane >> 3) & 1);

    float acc[2][8][4];
    #pragma unroll
    for (int mf = 0; mf < 2; mf++)
        #pragma unroll
        for (int nf = 0; nf < 8; nf++)
            #pragma unroll
            for (int j = 0; j < 4; j++) acc[mf][nf][j] = 0.0f;

    const uint32_t sbase = sm_u32(smg);
    auto load_stage = [&](int stage, int kc) {
        uint32_t ab = sbase + stage * (GSTAGE * 2);
        uint32_t wb = ab + GTILE * 2;
        #pragma unroll
        for (int i = 0; i < 2; i++) {
            int gi = tid + i * 256;
            int r = gi >> 2, c = gi & 3;
            cp16(ab + (r * GSTR + c * 8) * 2, A + (size_t)(m0 + r) * DMODEL + kc + c * 8);
            cp16(wb + (r * GSTR + c * 8) * 2, W + (size_t)(n0 + r) * DMODEL + kc + c * 8);
        }
        cp_commit();
    };

    load_stage(0, 0);
    load_stage(1, 32);

    const int NCHUNK = DMODEL / 32;
    for (int c = 0; c < NCHUNK; c++) {
        cp_wait<1>();
        __syncthreads();
        if (c + 2 < NCHUNK)
            load_stage((c + 2) % 3, (c + 2) * 32);

        const __half* Sb = smg + (c % 3) * GSTAGE;
        const uint32_t aA0 = sm_u32(Sb + (wm * 32 + a_row) * GSTR + a_col);
        const uint32_t aA1 = aA0 + 16 * GSTR * 2;
        const uint32_t aB  = sm_u32(Sb + GTILE + (wn * 64 + b_row) * GSTR + b_col);

        #pragma unroll
        for (int kk = 0; kk < 2; kk++) {
            uint32_t af0[4], af1[4];
            ldsm4(aA0 + kk * 32, af0[0], af0[1], af0[2], af0[3]);
            ldsm4(aA1 + kk * 32, af1[0], af1[1], af1[2], af1[3]);
            #pragma unroll
            for (int p = 0; p < 4; p++) {
                uint32_t b0, b1, b2, b3;
                ldsm4(aB + (p * 16 * GSTR) * 2 + kk * 32, b0, b1, b2, b3);
                uint32_t bf0[2] = {b0, b1};
                uint32_t bf1[2] = {b2, b3};
                mma_f16(acc[0][2*p],     af0, bf0);
                mma_f16(acc[1][2*p],     af1, bf0);
                mma_f16(acc[0][2*p + 1], af0, bf1);
                mma_f16(acc[1][2*p + 1], af1, bf1);
            }
        }
        __syncthreads();
    }

    #pragma unroll
    for (int mf = 0; mf < 2; mf++) {
        int row0 = m0 + wm * 32 + mf * 16 + g;
        #pragma unroll
        for (int nf = 0; nf < 8; nf++) {
            int col = n0 + wn * 64 + nf * 8 + 2 * q;
            float b0 = __ldg(bias + col);
            float b1 = __ldg(bias + col + 1);
            float v00 = acc[mf][nf][0] + b0, v01 = acc[mf][nf][1] + b1;
            float v10 = acc[mf][nf][2] + b0, v11 = acc[mf][nf][3] + b1;
            if (mode) {
                __half* Ch = (__half*)Cout;
                *(__half2*)(Ch + (size_t)row0 * DMODEL + col) =
                    __floats2half2_rn(v00 * oscale, v01 * oscale);
                *(__half2*)(Ch + (size_t)(row0 + 8) * DMODEL + col) =
                    __floats2half2_rn(v10 * oscale, v11 * oscale);
            } else {
                float* Cf = (float*)Cout;
                *(float2*)(Cf + (size_t)row0 * DMODEL + col) = make_float2(v00, v01);
                *(float2*)(Cf + (size_t)(row0 + 8) * DMODEL + col) = make_float2(v10, v11);
            }
        }
    }
}

// Single GEMM (output projection: half inputs, fp32 output)
__global__ __launch_bounds__(256, 2) void gemm_mma(
    const __half* __restrict__ A, const __half* __restrict__ W,
    const float* __restrict__ bias, float* __restrict__ C)
{
    extern __shared__ __align__(16) __half smg[];
    gemm_body(A, W, bias, C, 0, 1.0f, smg, blockIdx.y * 128, blockIdx.x * 128);
}

// Fused Q/K/V projections (half outputs; z=0 is Q with 0.125 scale)
struct QKVArgs {
    const __half *A0, *A1, *A2;
    const __half *W0, *W1, *W2;
    const float *b0, *b1, *b2;
    __half *O0, *O1, *O2;
};
__global__ __launch_bounds__(256, 2) void gemm_qkv(QKVArgs a)
{
    extern __shared__ __align__(16) __half smg[];
    const int z = blockIdx.z;
    const __half* A = (z == 0) ? a.A0 : (z == 1) ? a.A1 : a.A2;
    const __half* W = (z == 0) ? a.W0 : (z == 1) ? a.W1 : a.W2;
    const float* b  = (z == 0) ? a.b0 : (z == 1) ? a.b1 : a.b2;
    __half* O       = (z == 0) ? a.O0 : (z == 1) ? a.O1 : a.O2;
    float oscale    = (z == 0) ? 0.125f : 1.0f;
    gemm_body(A, W, b, O, 1, oscale, smg, blockIdx.y * 128, blockIdx.x * 128);
}

// ---------------------------------------------------------------------------
// Causal flash attention, fp16 mma.sync m16n8k16. Br = Bc = 64, 4 warps.
// Q/K/V fp16 (Q pre-scaled by 1/8). Online softmax in fp32.
// DOUBLE-buffered K and V ({K,V} pairs prefetched 2 tiles ahead); per
// iteration: 1 cp.async wait + 2 __syncthreads. Q frags hoisted.
// V consumed via ldmatrix.trans.
// smem: 6 tiles x 64 x 72 halves = 55,296 B -> 4 CTAs/SM.
// grid = (32, 64) heavy-first, block = 128.
// ---------------------------------------------------------------------------
#define HSTR 72
#define HTILE (64 * HSTR)
#define ATTN_SMEM (6 * HTILE * 2)    // 55,296 B

__global__ __launch_bounds__(128, 4) void attn_mma(
    const __half* __restrict__ Q,
    const __half* __restrict__ K,
    const __half* __restrict__ V,
    __half* __restrict__ Cx)
{
    extern __shared__ __align__(16) __half sma[];
    __half* Qs = sma;                               // [qrow][dk]
    __half* Ps = sma + HTILE;                       // [qrow][key]
    __half* Kb[2] = {sma + 2 * HTILE, sma + 3 * HTILE};  // [key][dk]
    __half* Vb[2] = {sma + 4 * HTILE, sma + 5 * HTILE};  // [key][dk]

    const int tid  = threadIdx.x;
    const int lane = tid & 31;
    const int w    = tid >> 5;
    const int g    = lane >> 2;
    const int q    = lane & 3;
    const int qt   = gridDim.x - 1 - blockIdx.x;   // heavy tiles first
    const int bh   = blockIdx.y;
    const int b    = bh >> 4;
    const int h    = bh & 15;
    const int q0   = qt * 64;

    const int a_row = (lane & 7) + 8 * ((lane >> 3) & 1);
    const int a_col = 8 * (lane >> 4);
    const int b_row = 8 * (lane >> 4) + (lane & 7);
    const int b_col = 8 * ((lane >> 3) & 1);

    const size_t base = ((size_t)b * SEQ) * DMODEL + (size_t)h * HDIM;

    auto load_tile = [&](__half* dst, const __half* src, int r0) {
        uint32_t db = sm_u32(dst);
        #pragma unroll
        for (int i = 0; i < 4; i++) {
            int gi = tid + i * 128;
            int r = gi >> 3, c = gi & 7;
            cp16(db + (r * HSTR + c * 8) * 2, src + base + (size_t)(r0 + r) * DMODEL + c * 8);
        }
    };

    // prologue: G0 = {Q, K0, V0}; G1 = {K1, V1} (if qt >= 1)
    load_tile(Qs, Q, q0);
    load_tile(Kb[0], K, 0);
    load_tile(Vb[0], V, 0);
    cp_commit();
    if (qt >= 1) {
        load_tile(Kb[1], K, 64);
        load_tile(Vb[1], V, 64);
        cp_commit();
    }

    const uint32_t aQ = sm_u32(Qs + (w * 16 + a_row) * HSTR + a_col);
    const uint32_t aP = sm_u32(Ps + (w * 16 + a_row) * HSTR + a_col);
    const uint32_t aK0 = sm_u32(Kb[0] + b_row * HSTR + b_col);
    const uint32_t aK1 = sm_u32(Kb[1] + b_row * HSTR + b_col);
    const int vrow = (lane & 7) + 8 * ((lane >> 3) & 1);
    const uint32_t aV0 = sm_u32(Vb[0] + vrow * HSTR + 8 * (lane >> 4));
    const uint32_t aV1 = sm_u32(Vb[1] + vrow * HSTR + 8 * (lane >> 4));

    // Q fragments hoisted once G0 is complete
    if (qt >= 1) cp_wait<1>(); else cp_wait<0>();
    __syncthreads();
    uint32_t qf[4][4];
    #pragma unroll
    for (int ks = 0; ks < 4; ks++)
        ldsm4(aQ + ks * 32, qf[ks][0], qf[ks][1], qf[ks][2], qf[ks][3]);

    float o[8][4];
    #pragma unroll
    for (int nf = 0; nf < 8; nf++)
        #pragma unroll
        for (int j = 0; j < 4; j++) o[nf][j] = 0.0f;
    float mi0 = -1e30f, mi1 = -1e30f, li0 = 0.0f, li1 = 0.0f;

    for (int kt = 0; kt <= qt; kt++) {
        const int cur = kt & 1;
        // {K(kt), V(kt)} complete once every group except the newest is done
        if (kt < qt) cp_wait<1>(); else cp_wait<0>();
        __syncthreads();

        // ---- S = Q @ K^T ----
        float s[8][4];
        #pragma unroll
        for (int nf = 0; nf < 8; nf++)
            #pragma unroll
            for (int j = 0; j < 4; j++) s[nf][j] = 0.0f;

        const uint32_t aK = cur ? aK1 : aK0;
        #pragma unroll
        for (int ks = 0; ks < 4; ks++) {
            #pragma unroll
            for (int p = 0; p < 4; p++) {
                uint32_t b0, b1, b2, b3;
                ldsm4(aK + (p * 16 * HSTR) * 2 + ks * 32, b0, b1, b2, b3);
                uint32_t bf0[2] = {b0, b1};
                uint32_t bf1[2] = {b2, b3};
                mma_f16(s[2*p],     qf[ks], bf0);
                mma_f16(s[2*p + 1], qf[ks], bf1);
            }
        }

        // ---- causal mask on the diagonal tile ----
        if (kt == qt) {
            int row0 = q0 + w * 16 + g;
            int row1 = row0 + 8;
            int k0 = kt * 64;
            #pragma unroll
            for (int nf = 0; nf < 8; nf++) {
                int c0 = k0 + nf * 8 + 2 * q;
                if (c0 > row0)     s[nf][0] = -1e30f;
                if (c0 + 1 > row0) s[nf][1] = -1e30f;
                if (c0 > row1)     s[nf][2] = -1e30f;
                if (c0 + 1 > row1) s[nf][3] = -1e30f;
            }
        }

        // ---- online softmax (fp32) ----
        float mx0 = -1e30f, mx1 = -1e30f;
        #pragma unroll
        for (int nf = 0; nf < 8; nf++) {
            mx0 = fmaxf(mx0, fmaxf(s[nf][0], s[nf][1]));
            mx1 = fmaxf(mx1, fmaxf(s[nf][2], s[nf][3]));
        }
        mx0 = fmaxf(mx0, __shfl_xor_sync(0xffffffffu, mx0, 1));
        mx0 = fmaxf(mx0, __shfl_xor_sync(0xffffffffu, mx0, 2));
        mx1 = fmaxf(mx1, __shfl_xor_sync(0xffffffffu, mx1, 1));
        mx1 = fmaxf(mx1, __shfl_xor_sync(0xffffffffu, mx1, 2));
        float mn0 = fmaxf(mi0, mx0);
        float mn1 = fmaxf(mi1, mx1);

        float rs0 = 0.0f, rs1 = 0.0f;
        #pragma unroll
        for (int nf = 0; nf < 8; nf++) {
            s[nf][0] = __expf(s[nf][0] - mn0);
            s[nf][1] = __expf(s[nf][1] - mn0);
            s[nf][2] = __expf(s[nf][2] - mn1);
            s[nf][3] = __expf(s[nf][3] - mn1);
            rs0 += s[nf][0] + s[nf][1];
            rs1 += s[nf][2] + s[nf][3];
        }
        rs0 += __shfl_xor_sync(0xffffffffu, rs0, 1);
        rs0 += __shfl_xor_sync(0xffffffffu, rs0, 2);
        rs1 += __shfl_xor_sync(0xffffffffu, rs1, 1);
        rs1 += __shfl_xor_sync(0xffffffffu, rs1, 2);

        float al0 = __expf(mi0 - mn0);
        float al1 = __expf(mi1 - mn1);
        li0 = li0 * al0 + rs0;
        li1 = li1 * al1 + rs1;
        mi0 = mn0;
        mi1 = mn1;
        #pragma unroll
        for (int nf = 0; nf < 8; nf++) {
            o[nf][0] *= al0;
            o[nf][1] *= al0;
            o[nf][2] *= al1;
            o[nf][3] *= al1;
        }

        // ---- P -> smem (fp16), per-warp private 16 rows ----
        #pragma unroll
        for (int nf = 0; nf < 8; nf++) {
            int r0 = w * 16 + g;
            int cc = nf * 8 + 2 * q;
            *(__half2*)&Ps[r0 * HSTR + cc]       = __floats2half2_rn(s[nf][0], s[nf][1]);
            *(__half2*)&Ps[(r0 + 8) * HSTR + cc] = __floats2half2_rn(s[nf][2], s[nf][3]);
        }
        __syncwarp();

        // ---- O += P @ V : A = Ps ldsm, B = Vb ldsm.trans ----
        const uint32_t aV = cur ? aV1 : aV0;
        #pragma unroll
        for (int ks = 0; ks < 4; ks++) {
            uint32_t af[4];
            ldsm4(aP + ks * 32, af[0], af[1], af[2], af[3]);
            #pragma unroll
            for (int p = 0; p < 4; p++) {
                uint32_t b0, b1, b2, b3;
                ldsm4t(aV + (ks * 16 * HSTR) * 2 + p * 32, b0, b1, b2, b3);
                uint32_t bf0[2] = {b0, b1};
                uint32_t bf1[2] = {b2, b3};
                mma_f16(o[2*p],     af, bf0);
                mma_f16(o[2*p + 1], af, bf1);
            }
        }

        // buffers for kt consumed by all warps -> prefetch {K,V}(kt+2) into them
        __syncthreads();
        if (kt + 2 <= qt) {
            load_tile(Kb[cur], K, (kt + 2) * 64);
            load_tile(Vb[cur], V, (kt + 2) * 64);
            cp_commit();
        }
    }

    // ---- epilogue: normalize, round to fp16 (input of O-proj), store ----
    float inv0 = 1.0f / li0;
    float inv1 = 1.0f / li1;
    int row0 = q0 + w * 16 + g;
    #pragma unroll
    for (int nf = 0; nf < 8; nf++) {
        int col = nf * 8 + 2 * q;
        *(__half2*)(Cx + base + (size_t)row0 * DMODEL + col) =
            __floats2half2_rn(o[nf][0] * inv0, o[nf][1] * inv0);
        *(__half2*)(Cx + base + (size_t)(row0 + 8) * DMODEL + col) =
            __floats2half2_rn(o[nf][2] * inv1, o[nf][3] * inv1);
    }
}

// ---------------------------------------------------------------------------
extern "C" void kernel_launch(void* const* d_in, const int* in_sizes, int n_in,
                              void* d_out, int out_size)
{
    const float* query = (const float*)d_in[0];
    const float* key   = (const float*)d_in[1];
    const float* value = (const float*)d_in[2];
    // d_in[3] = mask: constant causal tril; handled analytically.
    const float* wq = (const float*)d_in[4];
    const float* bq = (const float*)d_in[5];
    const float* wk = (const float*)d_in[6];
    const float* bk = (const float*)d_in[7];
    const float* wv = (const float*)d_in[8];
    const float* bv = (const float*)d_in[9];
    const float* wo = (const float*)d_in[10];
    const float* bo = (const float*)d_in[11];
    float* out = (float*)d_out;

    __half *Q, *K, *V, *C, *T, *Wr;
    cudaGetSymbolAddress((void**)&Q,  g_Q);
    cudaGetSymbolAddress((void**)&K,  g_K);
    cudaGetSymbolAddress((void**)&V,  g_V);
    cudaGetSymbolAddress((void**)&C,  g_C);
    cudaGetSymbolAddress((void**)&T,  g_T);
    cudaGetSymbolAddress((void**)&Wr, g_Wr);
    const size_t NA = (size_t)MROWS * DMODEL;
    const size_t NW = (size_t)DMODEL * DMODEL;
    __half* T0 = T;          __half* T1 = T + NA;      __half* T2 = T + 2 * NA;
    __half* W0 = Wr;         __half* W1 = Wr + NW;
    __half* W2 = Wr + 2*NW;  __half* W3 = Wr + 3 * NW;

    cudaFuncSetAttribute(gemm_mma,
                         cudaFuncAttributeMaxDynamicSharedMemorySize, GEMM_SMEM);
    cudaFuncSetAttribute(gemm_qkv,
                         cudaFuncAttributeMaxDynamicSharedMemorySize, GEMM_SMEM);
    cudaFuncSetAttribute(attn_mma,
                         cudaFuncAttributeMaxDynamicSharedMemorySize, ATTN_SMEM);

    const int nact4 = (int)(NA / 4);   // 2,097,152
    const int nw4   = (int)(NW / 4);   // 262,144

    // Batched fp16 rounding
    Round3Args ra = {query, key, value, T0, T1, T2};
    round3_kernel<<<dim3((nact4 + 255) / 256, 3), 256>>>(ra, nact4);
    Round4Args rw = {wq, wk, wv, wo, W0, W1, W2, W3};
    round4_kernel<<<dim3((nw4 + 255) / 256, 4), 256>>>(rw, nw4);

    // Fused Q/K/V projections (Q output pre-scaled by 1/8, fp16 outputs)
    QKVArgs qa = {T0, T1, T2, W0, W1, W2, bq, bk, bv, Q, K, V};
    dim3 gridQKV(DMODEL / 128, MROWS / 128, 3);   // (8, 64, 3)
    gemm_qkv<<<gridQKV, 256, GEMM_SMEM>>>(qa);

    // Attention (fp16 in/out)
    dim3 gridA(SEQ / 64, BATCH * NHEAD);          // (32, 64)
    attn_mma<<<gridA, 128, ATTN_SMEM>>>(Q, K, V, C);

    // Output projection (fp16 inputs, fp32 output)
    dim3 gridG(DMODEL / 128, MROWS / 128);        // (8, 64)
    gemm_mma<<<gridG, 256, GEMM_SMEM>>>(C, W3, bo, out);
}

// round 17
// speedup vs baseline: 1.0245x; 1.0245x over previous
#include <cuda_runtime.h>
#include <cuda_fp16.h>
#include <cstdint>
#include <math.h>

// Problem constants
#define BATCH 4
#define SEQ   2048
#define DMODEL 1024
#define NHEAD 16
#define HDIM  64
#define MROWS (BATCH * SEQ)   // 8192

// Scratch (allocation-free rule: __device__ globals). All fp16 intermediates.
__device__ __half g_Q[(size_t)MROWS * DMODEL];
__device__ __half g_K[(size_t)MROWS * DMODEL];
__device__ __half g_V[(size_t)MROWS * DMODEL];
__device__ __half g_C[(size_t)MROWS * DMODEL];
__device__ __half g_T[3][(size_t)MROWS * DMODEL];   // fp16-rounded activations
__device__ __half g_Wr[4][(size_t)DMODEL * DMODEL]; // fp16-rounded weights

// ---------------------------------------------------------------------------
// Helpers
// ---------------------------------------------------------------------------
__device__ __forceinline__ void mma_f16(float* c, const uint32_t* a, const uint32_t* b) {
    asm volatile(
        "mma.sync.aligned.m16n8k16.row.col.f32.f16.f16.f32 "
        "{%0,%1,%2,%3}, {%4,%5,%6,%7}, {%8,%9}, {%0,%1,%2,%3};"
        : "+f"(c[0]), "+f"(c[1]), "+f"(c[2]), "+f"(c[3])
        : "r"(a[0]), "r"(a[1]), "r"(a[2]), "r"(a[3]), "r"(b[0]), "r"(b[1]));
}
__device__ __forceinline__ uint32_t sm_u32(const void* p) {
    return (uint32_t)__cvta_generic_to_shared(p);
}
__device__ __forceinline__ void ldsm4(uint32_t addr, uint32_t& r0, uint32_t& r1,
                                      uint32_t& r2, uint32_t& r3) {
    asm volatile("ldmatrix.sync.aligned.m8n8.x4.shared.b16 {%0,%1,%2,%3}, [%4];"
                 : "=r"(r0), "=r"(r1), "=r"(r2), "=r"(r3) : "r"(addr));
}
__device__ __forceinline__ void ldsm4t(uint32_t addr, uint32_t& r0, uint32_t& r1,
                                       uint32_t& r2, uint32_t& r3) {
    asm volatile("ldmatrix.sync.aligned.m8n8.x4.trans.shared.b16 {%0,%1,%2,%3}, [%4];"
                 : "=r"(r0), "=r"(r1), "=r"(r2), "=r"(r3) : "r"(addr));
}
__device__ __forceinline__ void cp16(uint32_t saddr, const void* gaddr) {
    asm volatile("cp.async.cg.shared.global [%0], [%1], 16;"
                 :: "r"(saddr), "l"(gaddr));
}
__device__ __forceinline__ void cp_commit() {
    asm volatile("cp.async.commit_group;" ::: "memory");
}
template <int N>
__device__ __forceinline__ void cp_wait() {
    asm volatile("cp.async.wait_group %0;" :: "n"(N) : "memory");
}

// ---------------------------------------------------------------------------
// Batched fp32 -> fp16 rounding (round-to-nearest-even).
// ---------------------------------------------------------------------------
struct Round3Args { const float *i0, *i1, *i2; __half *o0, *o1, *o2; };
__global__ void round3_kernel(Round3Args a, int n4)
{
    int i = blockIdx.x * blockDim.x + threadIdx.x;
    if (i >= n4) return;
    const float* in = (blockIdx.y == 0) ? a.i0 : (blockIdx.y == 1) ? a.i1 : a.i2;
    __half* out     = (blockIdx.y == 0) ? a.o0 : (blockIdx.y == 1) ? a.o1 : a.o2;
    float4 v = ((const float4*)in)[i];
    ((__half2*)out)[2 * i]     = __floats2half2_rn(v.x, v.y);
    ((__half2*)out)[2 * i + 1] = __floats2half2_rn(v.z, v.w);
}
struct Round4Args { const float *i0, *i1, *i2, *i3; __half *o0, *o1, *o2, *o3; };
__global__ void round4_kernel(Round4Args a, int n4)
{
    int i = blockIdx.x * blockDim.x + threadIdx.x;
    if (i >= n4) return;
    const float* in;
    __half* out;
    switch (blockIdx.y) {
        case 0: in = a.i0; out = a.o0; break;
        case 1: in = a.i1; out = a.o1; break;
        case 2: in = a.i2; out = a.o2; break;
        default: in = a.i3; out = a.o3; break;
    }
    float4 v = ((const float4*)in)[i];
    ((__half2*)out)[2 * i]     = __floats2half2_rn(v.x, v.y);
    ((__half2*)out)[2 * i + 1] = __floats2half2_rn(v.z, v.w);
}

// ---------------------------------------------------------------------------
// GEMM core: C[M,N] = A[M,K] @ W[N,K]^T + bias[N], fp16 mma.sync m16n8k16.
// Pre-rounded fp16 inputs. 4-stage cp.async pipeline, ONE __syncthreads per
// chunk (top sync alone protects the stage overwritten 3 chunks ahead).
// CTA tile 128x128, BK=32, 8 warps. block = 256.
// mode 1: half out = rn_f16((acc+bias)*oscale). mode 0: fp32 out.
// ---------------------------------------------------------------------------
#define GSTR 40                       // halves per row (32 + 8 pad), 80 B
#define GTILE (128 * GSTR)            // halves per tile
#define GSTAGE (2 * GTILE)            // A + W
#define GEMM_SMEM (4 * GSTAGE * 2)    // 81,920 B

__device__ __forceinline__ void gemm_body(
    const __half* __restrict__ A, const __half* __restrict__ W,
    const float* __restrict__ bias, void* __restrict__ Cout,
    int mode, float oscale, __half* smg, int m0, int n0)
{
    const int tid  = threadIdx.x;
    const int lane = tid & 31;
    const int wid  = tid >> 5;
    const int wm   = wid & 3;
    const int wn   = wid >> 2;
    const int g    = lane >> 2;
    const int q    = lane & 3;

    const int a_row = (lane & 7) + 8 * ((lane >> 3) & 1);
    const int a_col = 8 * (lane >> 4);
    const int b_row = 8 * (lane >> 4) + (lane & 7);
    const int b_col = 8 * ((lane >> 3) & 1);

    float acc[2][8][4];
    #pragma unroll
    for (int mf = 0; mf < 2; mf++)
        #pragma unroll
        for (int nf = 0; nf < 8; nf++)
            #pragma unroll
            for (int j = 0; j < 4; j++) acc[mf][nf][j] = 0.0f;

    const uint32_t sbase = sm_u32(smg);
    auto load_stage = [&](int stage, int kc) {
        uint32_t ab = sbase + stage * (GSTAGE * 2);
        uint32_t wb = ab + GTILE * 2;
        #pragma unroll
        for (int i = 0; i < 2; i++) {
            int gi = tid + i * 256;
            int r = gi >> 2, c = gi & 3;
            cp16(ab + (r * GSTR + c * 8) * 2, A + (size_t)(m0 + r) * DMODEL + kc + c * 8);
            cp16(wb + (r * GSTR + c * 8) * 2, W + (size_t)(n0 + r) * DMODEL + kc + c * 8);
        }
        cp_commit();
    };

    load_stage(0, 0);
    load_stage(1, 32);
    load_stage(2, 64);

    const int NCHUNK = DMODEL / 32;
    for (int c = 0; c < NCHUNK; c++) {
        // 3 groups in flight; <=2 pending => chunk c complete
        cp_wait<2>();
        __syncthreads();
        // prefetch chunk c+3 into the stage consumed at c-1 (protected by the
        // sync above); empty commit keeps the group count invariant
        if (c + 3 < NCHUNK) load_stage((c + 3) & 3, (c + 3) * 32);
        else                cp_commit();

        const __half* Sb = smg + (c & 3) * GSTAGE;
        const uint32_t aA0 = sm_u32(Sb + (wm * 32 + a_row) * GSTR + a_col);
        const uint32_t aA1 = aA0 + 16 * GSTR * 2;
        const uint32_t aB  = sm_u32(Sb + GTILE + (wn * 64 + b_row) * GSTR + b_col);

        #pragma unroll
        for (int kk = 0; kk < 2; kk++) {
            uint32_t af0[4], af1[4];
            ldsm4(aA0 + kk * 32, af0[0], af0[1], af0[2], af0[3]);
            ldsm4(aA1 + kk * 32, af1[0], af1[1], af1[2], af1[3]);
            #pragma unroll
            for (int p = 0; p < 4; p++) {
                uint32_t b0, b1, b2, b3;
                ldsm4(aB + (p * 16 * GSTR) * 2 + kk * 32, b0, b1, b2, b3);
                uint32_t bf0[2] = {b0, b1};
                uint32_t bf1[2] = {b2, b3};
                mma_f16(acc[0][2*p],     af0, bf0);
                mma_f16(acc[1][2*p],     af1, bf0);
                mma_f16(acc[0][2*p + 1], af0, bf1);
                mma_f16(acc[1][2*p + 1], af1, bf1);
            }
        }
        // no trailing sync: next iteration's top sync provides the guarantee
    }

    #pragma unroll
    for (int mf = 0; mf < 2; mf++) {
        int row0 = m0 + wm * 32 + mf * 16 + g;
        #pragma unroll
        for (int nf = 0; nf < 8; nf++) {
            int col = n0 + wn * 64 + nf * 8 + 2 * q;
            float b0 = __ldg(bias + col);
            float b1 = __ldg(bias + col + 1);
            float v00 = acc[mf][nf][0] + b0, v01 = acc[mf][nf][1] + b1;
            float v10 = acc[mf][nf][2] + b0, v11 = acc[mf][nf][3] + b1;
            if (mode) {
                __half* Ch = (__half*)Cout;
                *(__half2*)(Ch + (size_t)row0 * DMODEL + col) =
                    __floats2half2_rn(v00 * oscale, v01 * oscale);
                *(__half2*)(Ch + (size_t)(row0 + 8) * DMODEL + col) =
                    __floats2half2_rn(v10 * oscale, v11 * oscale);
            } else {
                float* Cf = (float*)Cout;
                *(float2*)(Cf + (size_t)row0 * DMODEL + col) = make_float2(v00, v01);
                *(float2*)(Cf + (size_t)(row0 + 8) * DMODEL + col) = make_float2(v10, v11);
            }
        }
    }
}

// Single GEMM (output projection: half inputs, fp32 output)
__global__ __launch_bounds__(256, 2) void gemm_mma(
    const __half* __restrict__ A, const __half* __restrict__ W,
    const float* __restrict__ bias, float* __restrict__ C)
{
    extern __shared__ __align__(16) __half smg[];
    gemm_body(A, W, bias, C, 0, 1.0f, smg, blockIdx.y * 128, blockIdx.x * 128);
}

// Fused Q/K/V projections (half outputs; z=0 is Q with 0.125 scale)
struct QKVArgs {
    const __half *A0, *A1, *A2;
    const __half *W0, *W1, *W2;
    const float *b0, *b1, *b2;
    __half *O0, *O1, *O2;
};
__global__ __launch_bounds__(256, 2) void gemm_qkv(QKVArgs a)
{
    extern __shared__ __align__(16) __half smg[];
    const int z = blockIdx.z;
    const __half* A = (z == 0) ? a.A0 : (z == 1) ? a.A1 : a.A2;
    const __half* W = (z == 0) ? a.W0 : (z == 1) ? a.W1 : a.W2;
    const float* b  = (z == 0) ? a.b0 : (z == 1) ? a.b1 : a.b2;
    __half* O       = (z == 0) ? a.O0 : (z == 1) ? a.O1 : a.O2;
    float oscale    = (z == 0) ? 0.125f : 1.0f;
    gemm_body(A, W, b, O, 1, oscale, smg, blockIdx.y * 128, blockIdx.x * 128);
}

// ---------------------------------------------------------------------------
// Causal flash attention, fp16 mma.sync m16n8k16. Br = Bc = 64, 4 warps.
// Q/K/V fp16 (Q pre-scaled by 1/8). Online softmax in fp32.
// Single-buffered K and V, cp.async group-order pipelining, Q frags hoisted.
// V consumed via ldmatrix.trans. (Round-15 version — double-buffer measured
// neutral-negative and was reverted.)
// smem: 4 tiles x 64 x 72 halves = 36,864 B. launch_bounds(128, 4).
// grid = (32, 64) heavy-first, block = 128.
// ---------------------------------------------------------------------------
#define HSTR 72
#define HTILE (64 * HSTR)
#define ATTN_SMEM (4 * HTILE * 2)    // 36,864 B

__global__ __launch_bounds__(128, 4) void attn_mma(
    const __half* __restrict__ Q,
    const __half* __restrict__ K,
    const __half* __restrict__ V,
    __half* __restrict__ Cx)
{
    extern __shared__ __align__(16) __half sma[];
    __half* Qs = sma;                // [qrow][dk]
    __half* Ks = sma + HTILE;        // [key][dk]
    __half* Ps = sma + 2 * HTILE;    // [qrow][key]
    __half* Vs = sma + 3 * HTILE;    // [key][dk] natural; consumed via ldsm.trans

    const int tid  = threadIdx.x;
    const int lane = tid & 31;
    const int w    = tid >> 5;
    const int g    = lane >> 2;
    const int q    = lane & 3;
    const int qt   = gridDim.x - 1 - blockIdx.x;   // heavy tiles first
    const int bh   = blockIdx.y;
    const int b    = bh >> 4;
    const int h    = bh & 15;
    const int q0   = qt * 64;

    const int a_row = (lane & 7) + 8 * ((lane >> 3) & 1);
    const int a_col = 8 * (lane >> 4);
    const int b_row = 8 * (lane >> 4) + (lane & 7);
    const int b_col = 8 * ((lane >> 3) & 1);

    const size_t base = ((size_t)b * SEQ) * DMODEL + (size_t)h * HDIM;

    auto load_tile = [&](__half* dst, const __half* src, int r0) {
        uint32_t db = sm_u32(dst);
        #pragma unroll
        for (int i = 0; i < 4; i++) {
            int gi = tid + i * 128;
            int r = gi >> 3, c = gi & 7;
            cp16(db + (r * HSTR + c * 8) * 2, src + base + (size_t)(r0 + r) * DMODEL + c * 8);
        }
    };

    // prologue: group A = Q + K0, group B = V0
    load_tile(Qs, Q, q0);
    load_tile(Ks, K, 0);
    cp_commit();
    load_tile(Vs, V, 0);
    cp_commit();

    const uint32_t aQ = sm_u32(Qs + (w * 16 + a_row) * HSTR + a_col);
    const uint32_t aP = sm_u32(Ps + (w * 16 + a_row) * HSTR + a_col);
    const uint32_t aK = sm_u32(Ks + b_row * HSTR + b_col);
    const uint32_t aV = sm_u32(Vs + ((lane & 7) + 8 * ((lane >> 3) & 1)) * HSTR
                                   + 8 * (lane >> 4));

    // Q fragments: loop-invariant (4 k16 steps), hoisted after prologue wait
    cp_wait<1>();
    __syncthreads();
    uint32_t qf[4][4];
    #pragma unroll
    for (int ks = 0; ks < 4; ks++)
        ldsm4(aQ + ks * 32, qf[ks][0], qf[ks][1], qf[ks][2], qf[ks][3]);

    float o[8][4];
    #pragma unroll
    for (int nf = 0; nf < 8; nf++)
        #pragma unroll
        for (int j = 0; j < 4; j++) o[nf][j] = 0.0f;
    float mi0 = -1e30f, mi1 = -1e30f, li0 = 0.0f, li1 = 0.0f;

    for (int kt = 0; kt <= qt; kt++) {
        // K(kt) ready (all but newest group complete)
        cp_wait<1>();
        __syncthreads();

        // ---- S = Q @ K^T : 4 k16 steps x 8 nf ----
        float s[8][4];
        #pragma unroll
        for (int nf = 0; nf < 8; nf++)
            #pragma unroll
            for (int j = 0; j < 4; j++) s[nf][j] = 0.0f;

        #pragma unroll
        for (int ks = 0; ks < 4; ks++) {
            #pragma unroll
            for (int p = 0; p < 4; p++) {
                uint32_t b0, b1, b2, b3;
                ldsm4(aK + (p * 16 * HSTR) * 2 + ks * 32, b0, b1, b2, b3);
                uint32_t bf0[2] = {b0, b1};
                uint32_t bf1[2] = {b2, b3};
                mma_f16(s[2*p],     qf[ks], bf0);
                mma_f16(s[2*p + 1], qf[ks], bf1);
            }
        }

        // Ks fully consumed -> overwrite with K(kt+1)
        __syncthreads();
        if (kt < qt) {
            load_tile(Ks, K, (kt + 1) * 64);
            cp_commit();
        }

        // ---- causal mask on the diagonal tile ----
        if (kt == qt) {
            int row0 = q0 + w * 16 + g;
            int row1 = row0 + 8;
            int k0 = kt * 64;
            #pragma unroll
            for (int nf = 0; nf < 8; nf++) {
                int c0 = k0 + nf * 8 + 2 * q;
                if (c0 > row0)     s[nf][0] = -1e30f;
                if (c0 + 1 > row0) s[nf][1] = -1e30f;
                if (c0 > row1)     s[nf][2] = -1e30f;
                if (c0 + 1 > row1) s[nf][3] = -1e30f;
            }
        }

        // ---- online softmax (fp32) ----
        float mx0 = -1e30f, mx1 = -1e30f;
        #pragma unroll
        for (int nf = 0; nf < 8; nf++) {
            mx0 = fmaxf(mx0, fmaxf(s[nf][0], s[nf][1]));
            mx1 = fmaxf(mx1, fmaxf(s[nf][2], s[nf][3]));
        }
        mx0 = fmaxf(mx0, __shfl_xor_sync(0xffffffffu, mx0, 1));
        mx0 = fmaxf(mx0, __shfl_xor_sync(0xffffffffu, mx0, 2));
        mx1 = fmaxf(mx1, __shfl_xor_sync(0xffffffffu, mx1, 1));
        mx1 = fmaxf(mx1, __shfl_xor_sync(0xffffffffu, mx1, 2));
        float mn0 = fmaxf(mi0, mx0);
        float mn1 = fmaxf(mi1, mx1);

        float rs0 = 0.0f, rs1 = 0.0f;
        #pragma unroll
        for (int nf = 0; nf < 8; nf++) {
            s[nf][0] = __expf(s[nf][0] - mn0);
            s[nf][1] = __expf(s[nf][1] - mn0);
            s[nf][2] = __expf(s[nf][2] - mn1);
            s[nf][3] = __expf(s[nf][3] - mn1);
            rs0 += s[nf][0] + s[nf][1];
            rs1 += s[nf][2] + s[nf][3];
        }
        rs0 += __shfl_xor_sync(0xffffffffu, rs0, 1);
        rs0 += __shfl_xor_sync(0xffffffffu, rs0, 2);
        rs1 += __shfl_xor_sync(0xffffffffu, rs1, 1);
        rs1 += __shfl_xor_sync(0xffffffffu, rs1, 2);

        float al0 = __expf(mi0 - mn0);
        float al1 = __expf(mi1 - mn1);
        li0 = li0 * al0 + rs0;
        li1 = li1 * al1 + rs1;
        mi0 = mn0;
        mi1 = mn1;
        #pragma unroll
        for (int nf = 0; nf < 8; nf++) {
            o[nf][0] *= al0;
            o[nf][1] *= al0;
            o[nf][2] *= al1;
            o[nf][3] *= al1;
        }

        // ---- P -> smem (fp16), per-warp private 16 rows ----
        #pragma unroll
        for (int nf = 0; nf < 8; nf++) {
            int r0 = w * 16 + g;
            int cc = nf * 8 + 2 * q;
            *(__half2*)&Ps[r0 * HSTR + cc]       = __floats2half2_rn(s[nf][0], s[nf][1]);
            *(__half2*)&Ps[(r0 + 8) * HSTR + cc] = __floats2half2_rn(s[nf][2], s[nf][3]);
        }
        __syncwarp();

        // V(kt) ready (all but newest group; last iter: drain all)
        if (kt < qt) cp_wait<1>(); else cp_wait<0>();
        __syncthreads();

        // ---- O += P @ V : A = Ps ldsm, B = Vs ldsm.trans ----
        #pragma unroll
        for (int ks = 0; ks < 4; ks++) {
            uint32_t af[4];
            ldsm4(aP + ks * 32, af[0], af[1], af[2], af[3]);
            #pragma unroll
            for (int p = 0; p < 4; p++) {
                uint32_t b0, b1, b2, b3;
                ldsm4t(aV + (ks * 16 * HSTR) * 2 + p * 32, b0, b1, b2, b3);
                uint32_t bf0[2] = {b0, b1};
                uint32_t bf1[2] = {b2, b3};
                mma_f16(o[2*p],     af, bf0);
                mma_f16(o[2*p + 1], af, bf1);
            }
        }

        // Vs fully consumed -> overwrite with V(kt+1)
        if (kt < qt) {
            __syncthreads();
            load_tile(Vs, V, (kt + 1) * 64);
            cp_commit();
        }
    }

    // ---- epilogue: normalize, round to fp16 (input of O-proj), store ----
    float inv0 = 1.0f / li0;
    float inv1 = 1.0f / li1;
    int row0 = q0 + w * 16 + g;
    #pragma unroll
    for (int nf = 0; nf < 8; nf++) {
        int col = nf * 8 + 2 * q;
        *(__half2*)(Cx + base + (size_t)row0 * DMODEL + col) =
            __floats2half2_rn(o[nf][0] * inv0, o[nf][1] * inv0);
        *(__half2*)(Cx + base + (size_t)(row0 + 8) * DMODEL + col) =
            __floats2half2_rn(o[nf][2] * inv1, o[nf][3] * inv1);
    }
}

// ---------------------------------------------------------------------------
extern "C" void kernel_launch(void* const* d_in, const int* in_sizes, int n_in,
                              void* d_out, int out_size)
{
    const float* query = (const float*)d_in[0];
    const float* key   = (const float*)d_in[1];
    const float* value = (const float*)d_in[2];
    // d_in[3] = mask: constant causal tril; handled analytically.
    const float* wq = (const float*)d_in[4];
    const float* bq = (const float*)d_in[5];
    const float* wk = (const float*)d_in[6];
    const float* bk = (const float*)d_in[7];
    const float* wv = (const float*)d_in[8];
    const float* bv = (const float*)d_in[9];
    const float* wo = (const float*)d_in[10];
    const float* bo = (const float*)d_in[11];
    float* out = (float*)d_out;

    __half *Q, *K, *V, *C, *T, *Wr;
    cudaGetSymbolAddress((void**)&Q,  g_Q);
    cudaGetSymbolAddress((void**)&K,  g_K);
    cudaGetSymbolAddress((void**)&V,  g_V);
    cudaGetSymbolAddress((void**)&C,  g_C);
    cudaGetSymbolAddress((void**)&T,  g_T);
    cudaGetSymbolAddress((void**)&Wr, g_Wr);
    const size_t NA = (size_t)MROWS * DMODEL;
    const size_t NW = (size_t)DMODEL * DMODEL;
    __half* T0 = T;          __half* T1 = T + NA;      __half* T2 = T + 2 * NA;
    __half* W0 = Wr;         __half* W1 = Wr + NW;
    __half* W2 = Wr + 2*NW;  __half* W3 = Wr + 3 * NW;

    cudaFuncSetAttribute(gemm_mma,
                         cudaFuncAttributeMaxDynamicSharedMemorySize, GEMM_SMEM);
    cudaFuncSetAttribute(gemm_qkv,
                         cudaFuncAttributeMaxDynamicSharedMemorySize, GEMM_SMEM);
    cudaFuncSetAttribute(attn_mma,
                         cudaFuncAttributeMaxDynamicSharedMemorySize, ATTN_SMEM);

    const int nact4 = (int)(NA / 4);   // 2,097,152
    const int nw4   = (int)(NW / 4);   // 262,144

    // Batched fp16 rounding
    Round3Args ra = {query, key, value, T0, T1, T2};
    round3_kernel<<<dim3((nact4 + 255) / 256, 3), 256>>>(ra, nact4);
    Round4Args rw = {wq, wk, wv, wo, W0, W1, W2, W3};
    round4_kernel<<<dim3((nw4 + 255) / 256, 4), 256>>>(rw, nw4);

    // Fused Q/K/V projections (Q output pre-scaled by 1/8, fp16 outputs)
    QKVArgs qa = {T0, T1, T2, W0, W1, W2, bq, bk, bv, Q, K, V};
    dim3 gridQKV(DMODEL / 128, MROWS / 128, 3);   // (8, 64, 3)
    gemm_qkv<<<gridQKV, 256, GEMM_SMEM>>>(qa);

    // Attention (fp16 in/out)
    dim3 gridA(SEQ / 64, BATCH * NHEAD);          // (32, 64)
    attn_mma<<<gridA, 128, ATTN_SMEM>>>(Q, K, V, C);

    // Output projection (fp16 inputs, fp32 output)
    dim3 gridG(DMODEL / 128, MROWS / 128);        // (8, 64)
    gemm_mma<<<gridG, 256, GEMM_SMEM>>>(C, W3, bo, out);
}